// round 9
// baseline (speedup 1.0000x reference)
#include <cuda_runtime.h>
#include <cstdint>

// Shapes (fixed)
#define NB 4
#define NG 4096
#define DZ 128
#define NT 2048

// Tiling
#define MT 32              // t rows per CTA (2 m16 tiles per warp)
#define GC 64              // g per chunk
#define NCHUNK (NG/GC)     // 64
#define ZROW 132           // u32 stride per g-pair row (pad 4 -> conflict-free)
#define TILE_U32 4608      // 32*ZROW (4224) + gmeta 256 + pad 128 = 128thr*9*4
#define TILE_BYTES (TILE_U32*4)     // 18432
#define NTHREADS 128       // 4 warps: 2 kk x 2 gs
#define PTHREADS 256

typedef unsigned int u32;

// Pre-packed tiles: [b][chunk][ Z f16x2 32xZROW | gmeta 64 x {xg0,xg1,Bg0,Bg1} | pad ]
__device__ __align__(16) u32 g_Zh[(size_t)NB * NCHUNK * TILE_U32];

__device__ __forceinline__ float ex2f(float x) {
    float y; asm("ex2.approx.f32 %0, %1;" : "=f"(y) : "f"(x)); return y;
}
__device__ __forceinline__ u32 f16x2(float lo, float hi) {
    u32 d; asm("cvt.rn.f16x2.f32 %0, %1, %2;" : "=r"(d) : "f"(hi), "f"(lo)); return d;
}
__device__ __forceinline__ u32 smem_u32(const void* p) {
    u32 a;
    asm("{ .reg .u64 t; cvta.to.shared.u64 t, %1; cvt.u32.u64 %0, t; }" : "=r"(a) : "l"(p));
    return a;
}
// NON-volatile MMA: register deps give correctness; ptxas may interleave freely.
__device__ __forceinline__ void mma16816(float* c, u32 a0, u32 a1, u32 a2, u32 a3,
                                         u32 b0, u32 b1) {
    asm("mma.sync.aligned.m16n8k16.row.col.f32.f16.f16.f32 "
        "{%0,%1,%2,%3}, {%4,%5,%6,%7}, {%8,%9}, {%0,%1,%2,%3};"
        : "+f"(c[0]), "+f"(c[1]), "+f"(c[2]), "+f"(c[3])
        : "r"(a0), "r"(a1), "r"(a2), "r"(a3), "r"(b0), "r"(b1));
}

// ---------------- prep: pack Z (f16x2, g-pairs, j-permuted) + gmeta ----------
__global__ void __launch_bounds__(PTHREADS)
prep_tiles(const float* __restrict__ zg_all, const float* __restrict__ xg_all,
           const float* __restrict__ lsp)
{
    const int bc  = blockIdx.x;          // b*NCHUNK + chunk
    const int b   = bc >> 6;
    const int gc  = bc & 63;
    const int tid = threadIdx.x;
    const int w   = tid >> 5;
    const int z4  = tid & 31;

    u32* tile = g_Zh + (size_t)bc * TILE_U32;
    const float* zbase = zg_all + ((size_t)b * NG + gc * GC) * DZ;

#pragma unroll
    for (int it = 0; it < 4; ++it) {
        int gp = w + it * 8;             // 0..31 (g-pair)
        float4 v0 = __ldg((const float4*)(zbase + (size_t)(2 * gp)     * DZ) + z4);
        float4 v1 = __ldg((const float4*)(zbase + (size_t)(2 * gp + 1) * DZ) + z4);
        u32* dst = tile + gp * ZROW;
        int p0 = (z4 & 1) * 64 + (z4 >> 1);     // perm p(z)=(z&7)*16+(z>>3)
        dst[p0]      = f16x2(v0.x, v1.x);
        dst[p0 + 16] = f16x2(v0.y, v1.y);
        dst[p0 + 32] = f16x2(v0.z, v1.z);
        dst[p0 + 48] = f16x2(v0.w, v1.w);
    }

    // gmeta: per g {xg0, xg1, Bg_k0, Bg_k1}, Bg_k = ck0*xg0^2 + ck1*xg1^2
    if (tid < GC) {
        const float HL2E = 0.7213475204444817f;
        float cc[2][2];
#pragma unroll
        for (int k = 0; k < 2; ++k)
#pragma unroll
            for (int d = 0; d < 2; ++d) {
                float p  = lsp[d * 2 + k];
                float sp = (p > 20.f) ? p : log1pf(expf(p));
                float iv = 1.f / (1e-5f + sp);
                cc[k][d] = -HL2E * iv * iv;
            }
        float2 xgv = __ldg((const float2*)xg_all + (size_t)b * NG + gc * GC + tid);
        float s0 = xgv.x * xgv.x, s1 = xgv.y * xgv.y;
        float Bg0 = fmaf(s0, cc[0][0], s1 * cc[0][1]);
        float Bg1 = fmaf(s0, cc[1][0], s1 * cc[1][1]);
        ((float4*)(tile + 32 * ZROW))[tid] = make_float4(xgv.x, xgv.y, Bg0, Bg1);
    }
}

// -------- A-fragment builder for one slice: gmeta float4s -> 8 packed halves --
__device__ __forceinline__ void build_a(
    float4 m0, float4 m1, float4 m2, float4 m3, int kk,
    const float* At, const float* u0, const float* u1, u32 (&a)[2][4])
{
    float B0 = kk ? m0.w : m0.z;
    float B1 = kk ? m1.w : m1.z;
    float B2 = kk ? m2.w : m2.z;
    float B3 = kk ? m3.w : m3.z;
    float wv[4][4];
#pragma unroll
    for (int rr = 0; rr < 4; ++rr) {
        wv[rr][0] = ex2f(fmaf(m0.x, u0[rr], fmaf(m0.y, u1[rr], B0)) + At[rr]);
        wv[rr][1] = ex2f(fmaf(m1.x, u0[rr], fmaf(m1.y, u1[rr], B1)) + At[rr]);
        wv[rr][2] = ex2f(fmaf(m2.x, u0[rr], fmaf(m2.y, u1[rr], B2)) + At[rr]);
        wv[rr][3] = ex2f(fmaf(m3.x, u0[rr], fmaf(m3.y, u1[rr], B3)) + At[rr]);
    }
#pragma unroll
    for (int m = 0; m < 2; ++m) {
        a[m][0] = f16x2(wv[2*m][0],   wv[2*m][1]);
        a[m][1] = f16x2(wv[2*m+1][0], wv[2*m+1][1]);
        a[m][2] = f16x2(wv[2*m][2],   wv[2*m][3]);
        a[m][3] = f16x2(wv[2*m+1][2], wv[2*m+1][3]);
    }
}

// -------- per-chunk compute: weights for BOTH slices first, then B-streamed MMAs
__device__ __forceinline__ void do_chunk(
    const u32* bu0, const u32* bu1, const float4* gm0, const float4* gm1,
    int kk, const float* At, const float* u0, const float* u1,
    float (&c)[2][16][4])
{
    // gmeta loads + both slices' A fragments (two independent MUFU chains)
    float4 n00 = gm0[0], n01 = gm0[1], n02 = gm0[8], n03 = gm0[9];
    float4 n10 = gm1[0], n11 = gm1[1], n12 = gm1[8], n13 = gm1[9];
    u32 a0[2][4], a1[2][4];
    build_a(n00, n01, n02, n03, kk, At, u0, u1, a0);
    build_a(n10, n11, n12, n13, kk, At, u0, u1, a1);

    // slice 0: stream B per m-group (2 LDS.128 -> 8 MMA)
    {
        const uint4* bup = (const uint4*)bu0;
        const uint4* blp = bup + ZROW;
#pragma unroll
        for (int m4 = 0; m4 < 4; ++m4) {
            uint4 BU = bup[m4], BL = blp[m4];
            const u32* b0p = (const u32*)&BU;
            const u32* b1p = (const u32*)&BL;
#pragma unroll
            for (int jj = 0; jj < 4; ++jj) {
                int j = m4 * 4 + jj;
                mma16816(c[0][j], a0[0][0], a0[0][1], a0[0][2], a0[0][3], b0p[jj], b1p[jj]);
                mma16816(c[1][j], a0[1][0], a0[1][1], a0[1][2], a0[1][3], b0p[jj], b1p[jj]);
            }
        }
    }
    // slice 1
    {
        const uint4* bup = (const uint4*)bu1;
        const uint4* blp = bup + ZROW;
#pragma unroll
        for (int m4 = 0; m4 < 4; ++m4) {
            uint4 BU = bup[m4], BL = blp[m4];
            const u32* b0p = (const u32*)&BU;
            const u32* b1p = (const u32*)&BL;
#pragma unroll
            for (int jj = 0; jj < 4; ++jj) {
                int j = m4 * 4 + jj;
                mma16816(c[0][j], a1[0][0], a1[0][1], a1[0][2], a1[0][3], b0p[jj], b1p[jj]);
                mma16816(c[1][j], a1[1][0], a1[1][1], a1[1][2], a1[1][3], b0p[jj], b1p[jj]);
            }
        }
    }
}

// ---------------- main: factored weights + HMMA, cp.async double buffer ------
__global__ void __launch_bounds__(NTHREADS, 2)
setconv_h(const float* __restrict__ xt_all,
          const float* __restrict__ lsp,
          float* __restrict__ out_all)
{
    __shared__ __align__(16) u32 smem[2 * TILE_U32];   // 36864 B; reused as red buf

    const int cta  = blockIdx.x;        // 256 CTAs
    const int b    = cta >> 6;
    const int t0   = (cta & 63) * MT;
    const int tid  = threadIdx.x;
    const int w    = tid >> 5;          // 0..3
    const int lane = tid & 31;
    const int kk   = w >> 1;            // RBF kernel index
    const int gs   = w & 1;             // g-split half
    const int q    = lane >> 2;         // 0..7
    const int r    = lane & 3;          // 0..3

    const u32 sbase = smem_u32(smem);
    const char* gtiles = (const char*)(g_Zh + (size_t)b * NCHUNK * TILE_U32);

    // RBF coefficients for this warp's k
    float cc0, cc1;
    {
        const float HL2E = 0.7213475204444817f;
        float p0 = lsp[0 * 2 + kk], p1 = lsp[1 * 2 + kk];
        float sp0 = (p0 > 20.f) ? p0 : log1pf(expf(p0));
        float sp1 = (p1 > 20.f) ? p1 : log1pf(expf(p1));
        float i0 = 1.f / (1e-5f + sp0), i1 = 1.f / (1e-5f + sp1);
        cc0 = -HL2E * i0 * i0;
        cc1 = -HL2E * i1 * i1;
    }

    // 4 rows: [0]=t0+q, [1]=t0+8+q (tile0); [2]=t0+16+q, [3]=t0+24+q (tile1)
    float At[4], u0[4], u1[4];
#pragma unroll
    for (int rr = 0; rr < 4; ++rr) {
        float2 xv = ((const float2*)xt_all)[(size_t)b * NT + t0 + rr * 8 + q];
        At[rr] = fmaf(xv.x * xv.x, cc0, xv.y * xv.y * cc1);
        u0[rr] = -2.f * cc0 * xv.x;
        u1[rr] = -2.f * cc1 * xv.y;
    }

    // hoisted smem offsets (stage 0)
    const u32* zb_bu0 = smem + (gs * 8 + r) * ZROW + q * 16;   // slice s=gs
    const u32* zb_bu1 = zb_bu0 + 16 * ZROW;                    // slice s=gs+2
    const float4* zb_gm0 = (const float4*)(smem + 32 * ZROW) + gs * 16 + 2 * r;
    const float4* zb_gm1 = zb_gm0 + 32;

    float c[2][16][4];
#pragma unroll
    for (int m = 0; m < 2; ++m)
#pragma unroll
        for (int j = 0; j < 16; ++j) {
            c[m][j][0] = 0.f; c[m][j][1] = 0.f; c[m][j][2] = 0.f; c[m][j][3] = 0.f;
        }

    const char* gsrc = gtiles + (size_t)tid * 16;   // chunk 0 src base

    // prologue: stage chunk 0 into stage 0 (9 segs x 2048B stride)
#pragma unroll
    for (int i = 0; i < 9; ++i)
        asm volatile("cp.async.cg.shared.global [%0], [%1], 16;"
                     :: "r"(sbase + tid * 16 + i * 2048), "l"(gsrc + i * 2048) : "memory");
    asm volatile("cp.async.commit_group;" ::: "memory");
    gsrc += TILE_BYTES;

#pragma unroll 1
    for (int gc = 0; gc < NCHUNK; gc += 2) {
#pragma unroll
        for (int st = 0; st < 2; ++st) {
            asm volatile("cp.async.wait_group 0;" ::: "memory");
            __syncthreads();
            if (gc + 1 + st < NCHUNK) {
                const u32 dstb = sbase + (1 - st) * TILE_BYTES + tid * 16;
#pragma unroll
                for (int i = 0; i < 9; ++i)
                    asm volatile("cp.async.cg.shared.global [%0], [%1], 16;"
                                 :: "r"(dstb + i * 2048), "l"(gsrc + i * 2048) : "memory");
                asm volatile("cp.async.commit_group;" ::: "memory");
            }
            gsrc += TILE_BYTES;
            do_chunk(zb_bu0 + st * TILE_U32, zb_bu1 + st * TILE_U32,
                     zb_gm0 + st * (TILE_U32 / 4), zb_gm1 + st * (TILE_U32 / 4),
                     kk, At, u0, u1, c);
        }
    }

    // ---- reduce g-split pairs via smem, then store ----
    __syncthreads();
    float4* red = (float4*)smem;       // 32KB needed <= 36864 available
    if (gs == 1) {
#pragma unroll
        for (int m = 0; m < 2; ++m)
#pragma unroll
            for (int j = 0; j < 16; ++j)
                red[((kk * 2 + m) * 16 + j) * 32 + lane] =
                    make_float4(c[m][j][0], c[m][j][1], c[m][j][2], c[m][j][3]);
    }
    __syncthreads();
    if (gs == 0) {
#pragma unroll
        for (int m = 0; m < 2; ++m) {
            float* oA = out_all + ((size_t)b * NT + t0 + m * 16 + q) * (DZ * 2) + kk;
            float* oB = oA + 8 * (DZ * 2);
#pragma unroll
            for (int j = 0; j < 16; ++j) {
                float4 v = red[((kk * 2 + m) * 16 + j) * 32 + lane];
                int n0 = 16 * j + 4 * r;
                oA[n0]     = c[m][j][0] + v.x;
                oA[n0 + 2] = c[m][j][1] + v.y;
                oB[n0]     = c[m][j][2] + v.z;
                oB[n0 + 2] = c[m][j][3] + v.w;
            }
        }
    }
}

extern "C" void kernel_launch(void* const* d_in, const int* in_sizes, int n_in,
                              void* d_out, int out_size)
{
    const float* xg  = (const float*)d_in[0];   // (4,64,64,2)
    const float* zg  = (const float*)d_in[1];   // (4,64,64,128)
    const float* xt  = (const float*)d_in[2];   // (4,2048,2)
    const float* lsp = (const float*)d_in[3];   // (2,2)
    float* out = (float*)d_out;                 // (4,2048,256)

    prep_tiles<<<NB * NCHUNK, PTHREADS>>>(zg, xg, lsp);
    setconv_h<<<NB * (NT / MT), NTHREADS>>>(xt, lsp, out);
}